// round 1
// baseline (speedup 1.0000x reference)
#include <cuda_runtime.h>
#include <stdint.h>

// Problem constants (from reference): B=16, L=4096, H=768 (fp32)
#define B_ 16
#define L_ 4096
#define H_ 768
#define H4 (H_ / 4)          // 192 float4 lanes per row
#define TOK_PER_BLK 16       // tokens handled per block
#define BLOCKS_PER_BATCH (L_ / TOK_PER_BLK)  // 256

// out[b, j, :] = sum over p in [lb(j), lb(j+1)) of x[b, p, :]
// where lb(t) = lower_bound over sorted seg[b, :] for value t.
__global__ __launch_bounds__(H4)
void token_segment_sum_kernel(const float* __restrict__ x,
                              const int*   __restrict__ seg,
                              float*       __restrict__ out)
{
    const int b    = blockIdx.x / BLOCKS_PER_BATCH;
    const int tile = blockIdx.x % BLOCKS_PER_BATCH;
    const int j0   = tile * TOK_PER_BLK;

    const int* __restrict__ segb = seg + b * L_;

    __shared__ int bnd[TOK_PER_BLK + 1];

    const int t = threadIdx.x;   // 0..191
    if (t <= TOK_PER_BLK) {
        // lower_bound: first index i with segb[i] >= (j0 + t)
        const int target = j0 + t;
        int lo = 0, hi = L_;
        #pragma unroll 1
        while (lo < hi) {
            int mid = (lo + hi) >> 1;
            if (segb[mid] < target) lo = mid + 1; else hi = mid;
        }
        bnd[t] = lo;
    }
    __syncthreads();

    const float4* __restrict__ xb =
        reinterpret_cast<const float4*>(x + (size_t)b * L_ * H_);
    float4* __restrict__ ob =
        reinterpret_cast<float4*>(out + (size_t)b * L_ * H_);

    // each thread owns one float4 lane (h4 = t) across all T tokens
    #pragma unroll
    for (int jj = 0; jj < TOK_PER_BLK; jj++) {
        const int s = bnd[jj];
        const int e = bnd[jj + 1];
        float4 acc = make_float4(0.f, 0.f, 0.f, 0.f);
        for (int p = s; p < e; p++) {
            float4 v = __ldg(&xb[(size_t)p * H4 + t]);
            acc.x += v.x; acc.y += v.y; acc.z += v.z; acc.w += v.w;
        }
        ob[(size_t)(j0 + jj) * H4 + t] = acc;
    }
}

extern "C" void kernel_launch(void* const* d_in, const int* in_sizes, int n_in,
                              void* d_out, int out_size)
{
    const float* x   = (const float*)d_in[0];   // sequence_output  [B, L, H] f32
    const int*   seg = (const int*)  d_in[1];   // wordpiece_to_token [B, L] i32
    float*       out = (float*)d_out;           // [B, L, H] f32

    dim3 grid(B_ * BLOCKS_PER_BATCH);           // 4096 blocks
    dim3 block(H4);                             // 192 threads
    token_segment_sum_kernel<<<grid, block>>>(x, seg, out);
}

// round 2
// speedup vs baseline: 1.0807x; 1.0807x over previous
#include <cuda_runtime.h>
#include <stdint.h>

// Problem constants: B=16, L=4096, H=768 (fp32)
#define B_ 16
#define L_ 4096
#define H_ 768
#define H4 (H_ / 4)            // 192 float4 lanes per row
#define TOK_PER_BLK 16         // tokens per block tile
#define CH 8                   // rows loaded per chunk (per-thread MLP)
#define BLOCKS_PER_BATCH (L_ / TOK_PER_BLK)  // 256

__global__ __launch_bounds__(H4)
void token_segment_sum_kernel(const float* __restrict__ x,
                              const int*   __restrict__ seg,
                              float*       __restrict__ out)
{
    const int b    = blockIdx.x / BLOCKS_PER_BATCH;
    const int tile = blockIdx.x % BLOCKS_PER_BATCH;
    const int j0   = tile * TOK_PER_BLK;

    const int* __restrict__ segb = seg + b * L_;

    __shared__ int bnd[TOK_PER_BLK + 1];

    const int t = threadIdx.x;   // 0..191 (float4 lane)
    if (t <= TOK_PER_BLK) {
        // lower_bound: first index i with segb[i] >= (j0 + t)
        const int target = j0 + t;
        int lo = 0, hi = L_;
        #pragma unroll 1
        while (lo < hi) {
            int mid = (lo + hi) >> 1;
            if (segb[mid] < target) lo = mid + 1; else hi = mid;
        }
        bnd[t] = lo;
    }
    __syncthreads();

    const float4* __restrict__ xb =
        reinterpret_cast<const float4*>(x + (size_t)b * L_ * H_);
    float4* __restrict__ ob =
        reinterpret_cast<float4*>(out + (size_t)b * L_ * H_);

    const int s0 = bnd[0];
    const int s1 = bnd[TOK_PER_BLK];

    // token cursor within the tile; all threads follow identical control flow
    int j = 0;

    // flush tokens that are empty at the very start (bnd[j+1] == s0)
    #pragma unroll 1
    while (j < TOK_PER_BLK && bnd[j + 1] == s0) {
        ob[(size_t)(j0 + j) * H4 + t] = make_float4(0.f, 0.f, 0.f, 0.f);
        j++;
    }

    float4 acc = make_float4(0.f, 0.f, 0.f, 0.f);

    // stream contiguous rows [s0, s1) in chunks of CH — CH independent loads
    #pragma unroll 1
    for (int base = s0; base < s1; base += CH) {
        const int n = min(CH, s1 - base);

        float4 v[CH];
        #pragma unroll
        for (int i = 0; i < CH; i++) {
            if (i < n)
                v[i] = __ldg(&xb[(size_t)(base + i) * H4 + t]);
        }

        #pragma unroll
        for (int i = 0; i < CH; i++) {
            if (i < n) {
                acc.x += v[i].x; acc.y += v[i].y;
                acc.z += v[i].z; acc.w += v[i].w;
                const int pos1 = base + i + 1;
                // flush every token ending exactly here (handles empty tokens:
                // consecutive equal boundaries store zero since acc was reset)
                #pragma unroll 1
                while (j < TOK_PER_BLK && bnd[j + 1] == pos1) {
                    ob[(size_t)(j0 + j) * H4 + t] = acc;
                    acc = make_float4(0.f, 0.f, 0.f, 0.f);
                    j++;
                }
            }
        }
    }
}

extern "C" void kernel_launch(void* const* d_in, const int* in_sizes, int n_in,
                              void* d_out, int out_size)
{
    const float* x   = (const float*)d_in[0];   // sequence_output  [B, L, H] f32
    const int*   seg = (const int*)  d_in[1];   // wordpiece_to_token [B, L] i32
    float*       out = (float*)d_out;           // [B, L, H] f32

    dim3 grid(B_ * BLOCKS_PER_BATCH);           // 4096 blocks
    dim3 block(H4);                             // 192 threads
    token_segment_sum_kernel<<<grid, block>>>(x, seg, out);
}

// round 3
// speedup vs baseline: 1.1211x; 1.0374x over previous
#include <cuda_runtime.h>
#include <stdint.h>

// Problem constants: B=16, L=4096, H=768 (fp32)
#define B_ 16
#define L_ 4096
#define H_ 768
#define H4 (H_ / 4)            // 192 float4 lanes per row
#define TOK_PER_BLK 16         // tokens per block tile
#define CH 4                   // rows per chunk (double-buffered => 4-8 in flight)
#define BLOCKS_PER_BATCH (L_ / TOK_PER_BLK)  // 256

__global__ __launch_bounds__(H4, 5)
void token_segment_sum_kernel(const float* __restrict__ x,
                              const int*   __restrict__ seg,
                              float*       __restrict__ out)
{
    const int b    = blockIdx.x / BLOCKS_PER_BATCH;
    const int tile = blockIdx.x % BLOCKS_PER_BATCH;
    const int j0   = tile * TOK_PER_BLK;

    const int* __restrict__ segb = seg + b * L_;

    __shared__ int bnd[TOK_PER_BLK + 1];

    const int t = threadIdx.x;   // 0..191 (float4 lane)
    if (t <= TOK_PER_BLK) {
        // lower_bound: first index i with segb[i] >= (j0 + t)
        const int target = j0 + t;
        int lo = 0, hi = L_;
        #pragma unroll 1
        while (lo < hi) {
            int mid = (lo + hi) >> 1;
            if (segb[mid] < target) lo = mid + 1; else hi = mid;
        }
        bnd[t] = lo;
    }
    __syncthreads();

    const float4* __restrict__ xb =
        reinterpret_cast<const float4*>(x + (size_t)b * L_ * H_);
    float4* __restrict__ ob =
        reinterpret_cast<float4*>(out + (size_t)b * L_ * H_);

    const int s0 = bnd[0];
    const int s1 = bnd[TOK_PER_BLK];

    int j = 0;

    // flush tokens that are empty at the very start (bnd[j+1] == s0)
    #pragma unroll 1
    while (j < TOK_PER_BLK && bnd[j + 1] == s0) {
        __stcs(&ob[(size_t)(j0 + j) * H4 + t], make_float4(0.f, 0.f, 0.f, 0.f));
        j++;
    }

    if (s0 == s1) return;   // whole tile was empty tokens

    float4 acc = make_float4(0.f, 0.f, 0.f, 0.f);

    // load n (<=CH) rows starting at 'bse' into v — CH independent LDGs
    auto loadc = [&](float4* v, int bse, int n) {
        #pragma unroll
        for (int i = 0; i < CH; i++)
            if (i < n)
                v[i] = __ldcs(&xb[(size_t)(bse + i) * H4 + t]);
    };

    // accumulate n rows of v, flushing tokens at boundaries from bnd[]
    auto drain = [&](const float4* v, int bse, int n) {
        #pragma unroll
        for (int i = 0; i < CH; i++) {
            if (i < n) {
                acc.x += v[i].x; acc.y += v[i].y;
                acc.z += v[i].z; acc.w += v[i].w;
                const int pos1 = bse + i + 1;
                #pragma unroll 1
                while (j < TOK_PER_BLK && bnd[j + 1] == pos1) {
                    __stcs(&ob[(size_t)(j0 + j) * H4 + t], acc);
                    acc = make_float4(0.f, 0.f, 0.f, 0.f);
                    j++;
                }
            }
        }
    };

    float4 vA[CH], vB[CH];

    int baseA = s0;
    int nA = min(CH, s1 - baseA);
    loadc(vA, baseA, nA);

    #pragma unroll 1
    while (true) {
        // issue next chunk (B) BEFORE draining A — keeps load pipe fed
        const int baseB = baseA + CH;
        const int nB = min(CH, s1 - baseB);   // may be <= 0
        loadc(vB, baseB, nB);
        drain(vA, baseA, nA);
        if (nB <= 0) break;

        const int baseC = baseB + CH;
        const int nC = min(CH, s1 - baseC);   // may be <= 0
        loadc(vA, baseC, nC);
        drain(vB, baseB, nB);
        if (nC <= 0) break;

        baseA = baseC;
        nA = nC;
    }
}

extern "C" void kernel_launch(void* const* d_in, const int* in_sizes, int n_in,
                              void* d_out, int out_size)
{
    const float* x   = (const float*)d_in[0];   // sequence_output  [B, L, H] f32
    const int*   seg = (const int*)  d_in[1];   // wordpiece_to_token [B, L] i32
    float*       out = (float*)d_out;           // [B, L, H] f32

    dim3 grid(B_ * BLOCKS_PER_BATCH);           // 4096 blocks
    dim3 block(H4);                             // 192 threads
    token_segment_sum_kernel<<<grid, block>>>(x, seg, out);
}